// round 10
// baseline (speedup 1.0000x reference)
#include <cuda_runtime.h>
#include <cuda_fp16.h>
#include <cstdint>

#define BATCH 4096
#define D 256
#define N2 8192
#define NTILE 64                       // 8192 / 128
#define NBLK (NTILE * (NTILE + 1) / 2) // 2080
#define GRID_MAIN 296                  // 2 CTAs/SM * 148 SMs
#define GRID_PRO 256

// ---------------- device scratch (zero-initialized at module load; ----------------
// each kernel's "last block" restores the zeros for the next graph replay)
__device__ double   g_colsum[D];
__device__ float    g_sq[N2];
__device__ float    g_g0;
__device__ double   g_disc;
__device__ unsigned g_cnt_pro;
__device__ unsigned g_cnt_mma;
__device__ __align__(16) __half g_half[(size_t)N2 * D];

__device__ __forceinline__ uint32_t smem_u32(const void* p) {
    uint32_t a;
    asm("{ .reg .u64 t; cvta.to.shared.u64 t, %1; cvt.u32.u64 %0, t; }" : "=r"(a) : "l"(p));
    return a;
}
#define CP_ASYNC16(dst, src) asm volatile("cp.async.ca.shared.global [%0], [%1], 16;" :: "r"(dst), "l"(src))
#define CP_COMMIT()          asm volatile("cp.async.commit_group;" ::: "memory")
#define CP_WAIT(n)           asm volatile("cp.async.wait_group %0;" :: "n"(n) : "memory")

// ---------------- prologue: rowsq + fp16 convert + colsum + (last block) bandwidth ----------------
__global__ void prologue_kernel(const float* __restrict__ S, const float* __restrict__ T) {
    __shared__ float cs[256];
    __shared__ unsigned islast;
    const int tid = threadIdx.x, w = tid >> 5, lane = tid & 31;
    cs[tid] = 0.f;
    __syncthreads();
    float cp[8] = {0.f, 0.f, 0.f, 0.f, 0.f, 0.f, 0.f, 0.f};
    const int base = blockIdx.x * 32;
    #pragma unroll
    for (int r = 0; r < 4; ++r) {
        int row = base + r * 8 + w;
        const float* F = (row < BATCH) ? (S + (size_t)row * D) : (T + (size_t)(row - BATCH) * D);
        float4 a = ((const float4*)F)[lane];
        float4 b = ((const float4*)F)[lane + 32];
        cp[0] += a.x; cp[1] += a.y; cp[2] += a.z; cp[3] += a.w;
        cp[4] += b.x; cp[5] += b.y; cp[6] += b.z; cp[7] += b.w;
        float s = a.x*a.x + a.y*a.y + a.z*a.z + a.w*a.w
                + b.x*b.x + b.y*b.y + b.z*b.z + b.w*b.w;
        __half2* H = (__half2*)(g_half + (size_t)row * D);
        H[lane * 2 + 0]      = __floats2half2_rn(a.x, a.y);
        H[lane * 2 + 1]      = __floats2half2_rn(a.z, a.w);
        H[64 + lane * 2 + 0] = __floats2half2_rn(b.x, b.y);
        H[64 + lane * 2 + 1] = __floats2half2_rn(b.z, b.w);
        #pragma unroll
        for (int off = 16; off > 0; off >>= 1) s += __shfl_down_sync(0xffffffffu, s, off);
        if (lane == 0) g_sq[row] = s;
    }
    #pragma unroll
    for (int q = 0; q < 4; ++q) atomicAdd(&cs[4 * lane + q], cp[q]);
    #pragma unroll
    for (int q = 0; q < 4; ++q) atomicAdd(&cs[128 + 4 * lane + q], cp[4 + q]);
    __syncthreads();
    atomicAdd(&g_colsum[tid], (double)cs[tid]);

    // ---- last block computes the bandwidth inline ----
    __threadfence();
    if (tid == 0) islast = (atomicAdd(&g_cnt_pro, 1u) == GRID_PRO - 1) ? 1u : 0u;
    __syncthreads();
    if (islast) {
        __shared__ double rs[256], rc[256];
        float s = 0.f;
        for (int i = tid; i < N2; i += 256) s += g_sq[i];
        rs[tid] = (double)s;
        double v = g_colsum[tid];
        rc[tid] = v * v;
        g_colsum[tid] = 0.0;           // restore for next replay
        __syncthreads();
        for (int k = 128; k > 0; k >>= 1) {
            if (tid < k) { rs[tid] += rs[tid + k]; rc[tid] += rc[tid + k]; }
            __syncthreads();
        }
        if (tid == 0) {
            double sum_dist = 2.0 * (double)N2 * rs[0] - 2.0 * rc[0];
            double bandwidth = ((double)N2 * (double)N2 - (double)N2) / sum_dist;
            g_g0 = (float)(bandwidth / 4.0);   // / 2^(NUM_KERNELS//2)
            g_cnt_pro = 0;                     // restore counter
        }
    }
}

// arg = -d*g0*log2(e) (<= 0); 5-kernel sum via EX2 (MUFU) + repeated squaring
__device__ __forceinline__ float kern5e(float arg) {
    float e;
    asm("ex2.approx.ftz.f32 %0, %1;" : "=f"(e) : "f"(fminf(arg, 0.f)));
    float e2 = e * e, e4 = e2 * e2, e8 = e4 * e4;
    return e + e2 + e4 + e8 + e8 * e8;
}

// ---------------- main: persistent HMMA kernel, 3-stage cp.async ring ----------------
// stage s at s*32768: A at +0 (16KB), B at +16384 (16KB). Then sqj, red.
#define STAGE_BYTES 32768
#define SM_SQJ   98304
#define SM_RED   98816
#define SMEM_TOTAL 98848

__device__ __forceinline__ void tri_coords(int x, int& bi, int& bj) {
    bi = (int)((sqrtf(8.f * x + 1.f) - 1.f) * 0.5f);
    while ((bi + 1) * (bi + 2) / 2 <= x) bi++;
    while (bi * (bi + 1) / 2 > x) bi--;
    bj = x - bi * (bi + 1) / 2;
}

__global__ void __launch_bounds__(256, 2) mmd_mma(float* __restrict__ out) {
    extern __shared__ __align__(1024) uint8_t dsm[];
    float* sqj = (float*)(dsm + SM_SQJ);   // pre-scaled by ng
    float* red = (float*)(dsm + SM_RED);

    const int tid = threadIdx.x;
    const int wid = tid >> 5, lane = tid & 31;
    const int wm = wid & 3, wn = wid >> 2;
    const int g = lane >> 2, j4 = lane & 3;
    const uint32_t sb = smem_u32(dsm);

    // ldmatrix swizzled offsets within a 16KB stage (k-step XORs bits 5-6)
    uint32_t aoff[2], boff[4];
    {
        int rA = wm * 32 + (lane & 15);
        int ca = (lane >> 4) * 16;
        #pragma unroll
        for (int mi = 0; mi < 2; ++mi) {
            uint32_t b0 = (uint32_t)((rA + mi * 16) * 128 + ca);
            aoff[mi] = b0 ^ ((b0 >> 3) & 0x70);
        }
        int rB = wn * 64 + (lane & 7) + ((lane >= 16) ? 8 : 0);
        int cb = (((lane >> 3) & 1) ? 16 : 0);
        #pragma unroll
        for (int nj = 0; nj < 4; ++nj) {
            uint32_t b0 = (uint32_t)((rB + nj * 16) * 128 + cb);
            boff[nj] = b0 ^ ((b0 >> 3) & 0x70);
        }
    }
    uint32_t stoff[4];
    #pragma unroll
    for (int r = 0; r < 4; ++r) {
        uint32_t b0 = (uint32_t)(((tid >> 3) + r * 32) * 128 + (tid & 7) * 16);
        stoff[r] = b0 ^ ((b0 >> 3) & 0x70);
    }
    const int ldrow = tid >> 3, ldf4 = tid & 7;

    const float ng = -g_g0 * 1.44269504088896340736f;   // -g0*log2(e), < 0
    const float m2ng = -2.f * ng;
    double dacc = 0.0;

    auto prefetch = [&](int pi0, int pj0, int kc, uint32_t stagebase) {
        const __half* pa = g_half + (size_t)(pi0 + ldrow) * D + kc + ldf4 * 8;
        const __half* pb = g_half + (size_t)(pj0 + ldrow) * D + kc + ldf4 * 8;
        #pragma unroll
        for (int r = 0; r < 4; ++r) {
            CP_ASYNC16(sb + stagebase + stoff[r], pa + (size_t)r * 32 * D);
            CP_ASYNC16(sb + stagebase + 16384 + stoff[r], pb + (size_t)r * 32 * D);
        }
    };

    int x = blockIdx.x;
    int bi, bj;
    tri_coords(x, bi, bj);
    int i0 = bi * 128, j0 = bj * 128;

    // prologue: prefetch chunks 0,1 of first tile into stages 0,1
    prefetch(i0, j0, 0, 0);           CP_COMMIT();
    prefetch(i0, j0, 64, STAGE_BYTES); CP_COMMIT();
    int buf = 0;   // stage of the chunk about to be computed

    for (; x < NBLK; x += GRID_MAIN) {
        int xn = x + GRID_MAIN;
        int i0n = 0, j0n = 0;
        const bool hasnext = xn < NBLK;
        if (hasnext) {
            int bin, bjn;
            tri_coords(xn, bin, bjn);
            i0n = bin * 128; j0n = bjn * 128;
        }

        float acc[2][8][4];
        #pragma unroll
        for (int mi = 0; mi < 2; ++mi)
            #pragma unroll
            for (int ni = 0; ni < 8; ++ni)
                #pragma unroll
                for (int q = 0; q < 4; ++q) acc[mi][ni][q] = 0.f;

        #pragma unroll
        for (int c = 0; c < 4; ++c) {
            CP_WAIT(1);          // completes the group for chunk c
            __syncthreads();     // all warps done with stage (buf+2)%3's old data
            if (c == 0 && tid < 128) sqj[tid] = g_sq[j0 + tid] * ng;
            int pbuf = buf + 2; if (pbuf >= 3) pbuf -= 3;
            if (c < 2)            prefetch(i0, j0, (c + 2) * 64, (uint32_t)pbuf * STAGE_BYTES);
            else if (hasnext)     prefetch(i0n, j0n, (c - 2) * 64, (uint32_t)pbuf * STAGE_BYTES);
            CP_COMMIT();         // one group per chunk, possibly empty

            const uint32_t bufA = sb + (uint32_t)buf * STAGE_BYTES;
            const uint32_t bufB = bufA + 16384;
            #pragma unroll
            for (int ks = 0; ks < 4; ++ks) {
                uint32_t a[2][4], b[4][4];
                #pragma unroll
                for (int mi = 0; mi < 2; ++mi)
                    asm volatile("ldmatrix.sync.aligned.m8n8.x4.shared.b16 {%0,%1,%2,%3}, [%4];"
                        : "=r"(a[mi][0]), "=r"(a[mi][1]), "=r"(a[mi][2]), "=r"(a[mi][3])
                        : "r"(bufA + (aoff[mi] ^ (ks * 32))));
                #pragma unroll
                for (int nj = 0; nj < 4; ++nj)
                    asm volatile("ldmatrix.sync.aligned.m8n8.x4.shared.b16 {%0,%1,%2,%3}, [%4];"
                        : "=r"(b[nj][0]), "=r"(b[nj][1]), "=r"(b[nj][2]), "=r"(b[nj][3])
                        : "r"(bufB + (boff[nj] ^ (ks * 32))));
                #pragma unroll
                for (int mi = 0; mi < 2; ++mi)
                    #pragma unroll
                    for (int ni = 0; ni < 8; ++ni) {
                        uint32_t b0 = b[ni >> 1][(ni & 1) * 2];
                        uint32_t b1 = b[ni >> 1][(ni & 1) * 2 + 1];
                        asm volatile(
                            "mma.sync.aligned.m16n8k16.row.col.f32.f16.f16.f32 "
                            "{%0,%1,%2,%3}, {%4,%5,%6,%7}, {%8,%9}, {%0,%1,%2,%3};"
                            : "+f"(acc[mi][ni][0]), "+f"(acc[mi][ni][1]),
                              "+f"(acc[mi][ni][2]), "+f"(acc[mi][ni][3])
                            : "r"(a[mi][0]), "r"(a[mi][1]), "r"(a[mi][2]), "r"(a[mi][3]),
                              "r"(b0), "r"(b1));
                    }
            }
            ++buf; if (buf >= 3) buf -= 3;
        }

        // ---------------- epilogue (overlaps next tile's in-flight chunk loads) ----------------
        float sing[2][2];
        #pragma unroll
        for (int mi = 0; mi < 2; ++mi) {
            sing[mi][0] = g_sq[i0 + wm * 32 + mi * 16 + g] * ng;
            sing[mi][1] = g_sq[i0 + wm * 32 + mi * 16 + g + 8] * ng;
        }
        float accsum = 0.f;
        #pragma unroll
        for (int mi = 0; mi < 2; ++mi)
            #pragma unroll
            for (int ni = 0; ni < 8; ++ni) {
                int cb = wn * 64 + ni * 8 + 2 * j4;
                float sj0 = sqj[cb], sj1 = sqj[cb + 1];
                accsum += kern5e(fmaf(acc[mi][ni][0], m2ng, sing[mi][0] + sj0))
                        + kern5e(fmaf(acc[mi][ni][1], m2ng, sing[mi][0] + sj1))
                        + kern5e(fmaf(acc[mi][ni][2], m2ng, sing[mi][1] + sj0))
                        + kern5e(fmaf(acc[mi][ni][3], m2ng, sing[mi][1] + sj1));
            }
        const int tbi = i0 >> 7, tbj = j0 >> 7;
        float w = (((i0 < BATCH) == (j0 < BATCH)) ? 1.f : -1.f) * ((tbi == tbj) ? 1.f : 2.f);
        accsum *= w;
        #pragma unroll
        for (int off = 16; off > 0; off >>= 1)
            accsum += __shfl_down_sync(0xffffffffu, accsum, off);
        if (lane == 0) red[wid] = accsum;
        __syncthreads();
        if (tid == 0) {
            float s = 0.f;
            #pragma unroll
            for (int i = 0; i < 8; ++i) s += red[i];
            dacc += (double)s;
        }
        // next iteration's c==0 __syncthreads orders red/sqj reuse

        i0 = i0n; j0 = j0n;
    }
    if (tid == 0) atomicAdd(&g_disc, dacc);

    // ---- last CTA writes the output and restores state ----
    __threadfence();
    __shared__ unsigned lastc;
    if (tid == 0) lastc = (atomicAdd(&g_cnt_mma, 1u) == GRID_MAIN - 1) ? 1u : 0u;
    __syncthreads();
    if (lastc && tid == 0) {
        double dsum = atomicAdd(&g_disc, 0.0);   // atomic read, L2-coherent
        out[0] = (float)(dsum / (5.0 * (double)BATCH * (double)BATCH));
        g_disc = 0.0;
        g_cnt_mma = 0;
    }
}

extern "C" void kernel_launch(void* const* d_in, const int* in_sizes, int n_in,
                              void* d_out, int out_size) {
    const float* S = (const float*)d_in[0];
    const float* T = (const float*)d_in[1];
    cudaFuncSetAttribute(mmd_mma, cudaFuncAttributeMaxDynamicSharedMemorySize, SMEM_TOTAL);
    prologue_kernel<<<GRID_PRO, 256>>>(S, T);
    mmd_mma<<<GRID_MAIN, 256, SMEM_TOTAL>>>((float*)d_out);
}

// round 11
// speedup vs baseline: 1.0593x; 1.0593x over previous
#include <cuda_runtime.h>
#include <cuda_fp16.h>
#include <cstdint>

#define BATCH 4096
#define D 256
#define N2 8192
#define NTILE 64                       // 8192 / 128
#define NBLK (NTILE * (NTILE + 1) / 2) // 2080
#define GRID_MAIN 296                  // 2 CTAs/SM * 148 SMs (all co-resident)
#define PRO_BLKS 256

// ---------------- device scratch (zero-initialized at load; the kernel ----------------
// restores all of it before exit so graph replays see a clean state)
__device__ double   g_colsum[D];
__device__ float    g_sq[N2];
__device__ float    g_g0;
__device__ double   g_disc;
__device__ unsigned g_cnt_pro;
__device__ unsigned g_cnt_mma;
__device__ unsigned g_ready;
__device__ __align__(16) __half g_half[(size_t)N2 * D];

__device__ __forceinline__ uint32_t smem_u32(const void* p) {
    uint32_t a;
    asm("{ .reg .u64 t; cvta.to.shared.u64 t, %1; cvt.u32.u64 %0, t; }" : "=r"(a) : "l"(p));
    return a;
}
#define CP_ASYNC16(dst, src) asm volatile("cp.async.ca.shared.global [%0], [%1], 16;" :: "r"(dst), "l"(src))
#define CP_COMMIT()          asm volatile("cp.async.commit_group;" ::: "memory")
#define CP_WAIT(n)           asm volatile("cp.async.wait_group %0;" :: "n"(n) : "memory")

// arg = -d*g0*log2(e) (<= 0); 5-kernel sum via EX2 (MUFU) + repeated squaring
__device__ __forceinline__ float kern5e(float arg) {
    float e;
    asm("ex2.approx.ftz.f32 %0, %1;" : "=f"(e) : "f"(fminf(arg, 0.f)));
    float e2 = e * e, e4 = e2 * e2, e8 = e4 * e4;
    return e + e2 + e4 + e8 + e8 * e8;
}

// dynamic smem: [0,32K) A bufs, [32K,64K) B bufs, [64K,+512) sqj*ng, then red[8]
#define SM_A     0
#define SM_B     32768
#define SM_SQJ   65536
#define SM_RED   66048
#define SMEM_TOTAL 66112

__global__ void __launch_bounds__(256, 2) mmd_fused(const float* __restrict__ S,
                                                    const float* __restrict__ T,
                                                    float* __restrict__ out) {
    extern __shared__ __align__(1024) uint8_t dsm[];
    const int tid = threadIdx.x;
    const int wid = tid >> 5, lane = tid & 31;
    __shared__ unsigned s_flag;

    // ================= Phase A: prologue (CTAs 0..255) =================
    if (blockIdx.x < PRO_BLKS) {
        float* cs = (float*)dsm;
        cs[tid] = 0.f;
        __syncthreads();
        float cp[8] = {0.f, 0.f, 0.f, 0.f, 0.f, 0.f, 0.f, 0.f};
        const int base = blockIdx.x * 32;
        #pragma unroll
        for (int r = 0; r < 4; ++r) {
            int row = base + r * 8 + wid;
            const float* F = (row < BATCH) ? (S + (size_t)row * D) : (T + (size_t)(row - BATCH) * D);
            float4 a = ((const float4*)F)[lane];
            float4 b = ((const float4*)F)[lane + 32];
            cp[0] += a.x; cp[1] += a.y; cp[2] += a.z; cp[3] += a.w;
            cp[4] += b.x; cp[5] += b.y; cp[6] += b.z; cp[7] += b.w;
            float s = a.x*a.x + a.y*a.y + a.z*a.z + a.w*a.w
                    + b.x*b.x + b.y*b.y + b.z*b.z + b.w*b.w;
            __half2* H = (__half2*)(g_half + (size_t)row * D);
            H[lane * 2 + 0]      = __floats2half2_rn(a.x, a.y);
            H[lane * 2 + 1]      = __floats2half2_rn(a.z, a.w);
            H[64 + lane * 2 + 0] = __floats2half2_rn(b.x, b.y);
            H[64 + lane * 2 + 1] = __floats2half2_rn(b.z, b.w);
            #pragma unroll
            for (int off = 16; off > 0; off >>= 1) s += __shfl_down_sync(0xffffffffu, s, off);
            if (lane == 0) g_sq[row] = s;
        }
        #pragma unroll
        for (int q = 0; q < 4; ++q) atomicAdd(&cs[4 * lane + q], cp[q]);
        #pragma unroll
        for (int q = 0; q < 4; ++q) atomicAdd(&cs[128 + 4 * lane + q], cp[4 + q]);
        __syncthreads();
        atomicAdd(&g_colsum[tid], (double)cs[tid]);

        __threadfence();
        if (tid == 0) s_flag = (atomicAdd(&g_cnt_pro, 1u) == PRO_BLKS - 1) ? 1u : 0u;
        __syncthreads();
        if (s_flag) {
            // last prologue CTA: bandwidth, then release everyone
            double* rs = (double*)dsm;              // 2KB
            double* rc = (double*)(dsm + 2048);     // 2KB
            float s = 0.f;
            for (int i = tid; i < N2; i += 256) s += g_sq[i];
            rs[tid] = (double)s;
            double v = g_colsum[tid];
            rc[tid] = v * v;
            g_colsum[tid] = 0.0;                    // restore for next replay
            __syncthreads();
            for (int k = 128; k > 0; k >>= 1) {
                if (tid < k) { rs[tid] += rs[tid + k]; rc[tid] += rc[tid + k]; }
                __syncthreads();
            }
            if (tid == 0) {
                double sum_dist = 2.0 * (double)N2 * rs[0] - 2.0 * rc[0];
                double bandwidth = ((double)N2 * (double)N2 - (double)N2) / sum_dist;
                g_g0 = (float)(bandwidth / 4.0);    // / 2^(NUM_KERNELS//2)
                g_cnt_pro = 0;                      // restore counter
                __threadfence();
                atomicExch(&g_ready, 1u);
            }
        }
    }

    // ================= global barrier: wait for bandwidth =================
    if (tid == 0) {
        while (atomicAdd(&g_ready, 0u) == 0u) __nanosleep(64);
    }
    __syncthreads();

    // ================= Phase B: persistent HMMA mainloop (R9 structure) =================
    float* sqj = (float*)(dsm + SM_SQJ);   // pre-scaled by ng
    float* red = (float*)(dsm + SM_RED);
    const int wm = wid & 3, wn = wid >> 2;
    const int g = lane >> 2, j4 = lane & 3;
    const uint32_t sb = smem_u32(dsm);

    // ldmatrix swizzled offsets within a 16KB buffer (k-step XORs bits 5-6)
    uint32_t aoff[2], boff[4];
    {
        int rA = wm * 32 + (lane & 15);
        int ca = (lane >> 4) * 16;
        #pragma unroll
        for (int mi = 0; mi < 2; ++mi) {
            uint32_t b0 = (uint32_t)((rA + mi * 16) * 128 + ca);
            aoff[mi] = b0 ^ ((b0 >> 3) & 0x70);
        }
        int rB = wn * 64 + (lane & 7) + ((lane >= 16) ? 8 : 0);
        int cb = (((lane >> 3) & 1) ? 16 : 0);
        #pragma unroll
        for (int nj = 0; nj < 4; ++nj) {
            uint32_t b0 = (uint32_t)((rB + nj * 16) * 128 + cb);
            boff[nj] = b0 ^ ((b0 >> 3) & 0x70);
        }
    }
    uint32_t stoff[4];
    #pragma unroll
    for (int r = 0; r < 4; ++r) {
        uint32_t b0 = (uint32_t)(((tid >> 3) + r * 32) * 128 + (tid & 7) * 16);
        stoff[r] = b0 ^ ((b0 >> 3) & 0x70);
    }
    const int ldrow = tid >> 3, ldf4 = tid & 7;

    const float ng = -g_g0 * 1.44269504088896340736f;   // -g0*log2(e), < 0
    const float m2ng = -2.f * ng;
    double dacc = 0.0;

    int x = blockIdx.x;
    int bi = (int)((sqrtf(8.f * x + 1.f) - 1.f) * 0.5f);
    while ((bi + 1) * (bi + 2) / 2 <= x) bi++;
    while (bi * (bi + 1) / 2 > x) bi--;
    int bj = x - bi * (bi + 1) / 2;
    int i0 = bi * 128, j0 = bj * 128;

    // prefetch chunk 0 of first tile
    if (x < NBLK) {
        const __half* pa = g_half + (size_t)(i0 + ldrow) * D + ldf4 * 8;
        const __half* pb = g_half + (size_t)(j0 + ldrow) * D + ldf4 * 8;
        #pragma unroll
        for (int r = 0; r < 4; ++r) {
            CP_ASYNC16(sb + SM_A + stoff[r], pa + (size_t)r * 32 * D);
            CP_ASYNC16(sb + SM_B + stoff[r], pb + (size_t)r * 32 * D);
        }
        CP_COMMIT();
    }

    for (; x < NBLK; x += GRID_MAIN) {
        if (tid < 128) sqj[tid] = g_sq[j0 + tid] * ng;

        float acc[2][8][4];
        #pragma unroll
        for (int mi = 0; mi < 2; ++mi)
            #pragma unroll
            for (int ni = 0; ni < 8; ++ni)
                #pragma unroll
                for (int q = 0; q < 4; ++q) acc[mi][ni][q] = 0.f;

        #pragma unroll
        for (int c = 0; c < 4; ++c) {
            const uint32_t bufA = sb + SM_A + (c & 1) * 16384;
            const uint32_t bufB = sb + SM_B + (c & 1) * 16384;
            if (c < 3) {   // prefetch next chunk into other buffer
                const int kc = (c + 1) * 64;
                const uint32_t nbA = sb + SM_A + ((c + 1) & 1) * 16384;
                const uint32_t nbB = sb + SM_B + ((c + 1) & 1) * 16384;
                const __half* pa = g_half + (size_t)(i0 + ldrow) * D + kc + ldf4 * 8;
                const __half* pb = g_half + (size_t)(j0 + ldrow) * D + kc + ldf4 * 8;
                #pragma unroll
                for (int r = 0; r < 4; ++r) {
                    CP_ASYNC16(nbA + stoff[r], pa + (size_t)r * 32 * D);
                    CP_ASYNC16(nbB + stoff[r], pb + (size_t)r * 32 * D);
                }
                CP_COMMIT();
                CP_WAIT(1);
            } else {
                CP_WAIT(0);
            }
            __syncthreads();
            #pragma unroll
            for (int ks = 0; ks < 4; ++ks) {
                uint32_t a[2][4], b[4][4];
                #pragma unroll
                for (int mi = 0; mi < 2; ++mi)
                    asm volatile("ldmatrix.sync.aligned.m8n8.x4.shared.b16 {%0,%1,%2,%3}, [%4];"
                        : "=r"(a[mi][0]), "=r"(a[mi][1]), "=r"(a[mi][2]), "=r"(a[mi][3])
                        : "r"(bufA + (aoff[mi] ^ (ks * 32))));
                #pragma unroll
                for (int nj = 0; nj < 4; ++nj)
                    asm volatile("ldmatrix.sync.aligned.m8n8.x4.shared.b16 {%0,%1,%2,%3}, [%4];"
                        : "=r"(b[nj][0]), "=r"(b[nj][1]), "=r"(b[nj][2]), "=r"(b[nj][3])
                        : "r"(bufB + (boff[nj] ^ (ks * 32))));
                #pragma unroll
                for (int mi = 0; mi < 2; ++mi)
                    #pragma unroll
                    for (int ni = 0; ni < 8; ++ni) {
                        uint32_t b0 = b[ni >> 1][(ni & 1) * 2];
                        uint32_t b1 = b[ni >> 1][(ni & 1) * 2 + 1];
                        asm volatile(
                            "mma.sync.aligned.m16n8k16.row.col.f32.f16.f16.f32 "
                            "{%0,%1,%2,%3}, {%4,%5,%6,%7}, {%8,%9}, {%0,%1,%2,%3};"
                            : "+f"(acc[mi][ni][0]), "+f"(acc[mi][ni][1]),
                              "+f"(acc[mi][ni][2]), "+f"(acc[mi][ni][3])
                            : "r"(a[mi][0]), "r"(a[mi][1]), "r"(a[mi][2]), "r"(a[mi][3]),
                              "r"(b0), "r"(b1));
                    }
            }
            __syncthreads();
        }

        // issue next tile's chunk-0 prefetch before the epilogue (hides load latency)
        const int xi = i0, xj = j0, xbi = bi, xbj = bj;
        int xn = x + GRID_MAIN;
        if (xn < NBLK) {
            bi = (int)((sqrtf(8.f * xn + 1.f) - 1.f) * 0.5f);
            while ((bi + 1) * (bi + 2) / 2 <= xn) bi++;
            while (bi * (bi + 1) / 2 > xn) bi--;
            bj = xn - bi * (bi + 1) / 2;
            i0 = bi * 128; j0 = bj * 128;
            const __half* pa = g_half + (size_t)(i0 + ldrow) * D + ldf4 * 8;
            const __half* pb = g_half + (size_t)(j0 + ldrow) * D + ldf4 * 8;
            #pragma unroll
            for (int r = 0; r < 4; ++r) {
                CP_ASYNC16(sb + SM_A + stoff[r], pa + (size_t)r * 32 * D);
                CP_ASYNC16(sb + SM_B + stoff[r], pb + (size_t)r * 32 * D);
            }
            CP_COMMIT();
        }

        // ---------------- epilogue ----------------
        float sing[2][2];
        #pragma unroll
        for (int mi = 0; mi < 2; ++mi) {
            sing[mi][0] = g_sq[xi + wm * 32 + mi * 16 + g] * ng;
            sing[mi][1] = g_sq[xi + wm * 32 + mi * 16 + g + 8] * ng;
        }
        float accsum = 0.f;
        #pragma unroll
        for (int mi = 0; mi < 2; ++mi)
            #pragma unroll
            for (int ni = 0; ni < 8; ++ni) {
                int cb = wn * 64 + ni * 8 + 2 * j4;
                float sj0 = sqj[cb], sj1 = sqj[cb + 1];
                accsum += kern5e(fmaf(acc[mi][ni][0], m2ng, sing[mi][0] + sj0))
                        + kern5e(fmaf(acc[mi][ni][1], m2ng, sing[mi][0] + sj1))
                        + kern5e(fmaf(acc[mi][ni][2], m2ng, sing[mi][1] + sj0))
                        + kern5e(fmaf(acc[mi][ni][3], m2ng, sing[mi][1] + sj1));
            }
        float w = (((xi < BATCH) == (xj < BATCH)) ? 1.f : -1.f) * ((xbi == xbj) ? 1.f : 2.f);
        accsum *= w;
        #pragma unroll
        for (int off = 16; off > 0; off >>= 1)
            accsum += __shfl_down_sync(0xffffffffu, accsum, off);
        if (lane == 0) red[wid] = accsum;
        __syncthreads();
        if (tid == 0) {
            float s = 0.f;
            #pragma unroll
            for (int i = 0; i < 8; ++i) s += red[i];
            dacc += (double)s;
        }
        __syncthreads();   // red/sqj safe to reuse next tile
    }
    if (tid == 0) atomicAdd(&g_disc, dacc);

    // ---- last CTA writes the output and restores state for graph replay ----
    __threadfence();
    if (tid == 0) s_flag = (atomicAdd(&g_cnt_mma, 1u) == GRID_MAIN - 1) ? 1u : 0u;
    __syncthreads();
    if (s_flag && tid == 0) {
        double dsum = atomicAdd(&g_disc, 0.0);   // L2-coherent read
        out[0] = (float)(dsum / (5.0 * (double)BATCH * (double)BATCH));
        g_disc = 0.0;
        g_cnt_mma = 0;
        atomicExch(&g_ready, 0u);
    }
}

extern "C" void kernel_launch(void* const* d_in, const int* in_sizes, int n_in,
                              void* d_out, int out_size) {
    const float* S = (const float*)d_in[0];
    const float* T = (const float*)d_in[1];
    cudaFuncSetAttribute(mmd_fused, cudaFuncAttributeMaxDynamicSharedMemorySize, SMEM_TOTAL);
    mmd_fused<<<GRID_MAIN, 256, SMEM_TOTAL>>>(S, T, (float*)d_out);
}

// round 12
// speedup vs baseline: 1.1170x; 1.0545x over previous
#include <cuda_runtime.h>
#include <cuda_fp16.h>
#include <cstdint>

#define BATCH 4096
#define D 256
#define N2 8192
#define NTILE 64                       // 8192 / 128
#define NBLK (NTILE * (NTILE + 1) / 2) // 2080
#define GRID_MAIN 296                  // 2 CTAs/SM * 148 SMs (all co-resident)

// ---------------- device scratch (zero-initialized at load; the kernel ----------------
// restores everything before exit so graph replays see a clean state)
__device__ double   g_colsum[D];
__device__ double   g_sum_sq;
__device__ float    g_sq[N2];
__device__ float    g_g0;
__device__ double   g_disc;
__device__ unsigned g_cnt_pro;
__device__ unsigned g_cnt_mma;
__device__ unsigned g_conv;    // conversion complete -> mainloop may start
__device__ unsigned g_ready;   // g0 available -> epilogue may run
__device__ __align__(16) __half g_half[(size_t)N2 * D];

__device__ __forceinline__ uint32_t smem_u32(const void* p) {
    uint32_t a;
    asm("{ .reg .u64 t; cvta.to.shared.u64 t, %1; cvt.u32.u64 %0, t; }" : "=r"(a) : "l"(p));
    return a;
}
#define CP_ASYNC16(dst, src) asm volatile("cp.async.ca.shared.global [%0], [%1], 16;" :: "r"(dst), "l"(src))
#define CP_COMMIT()          asm volatile("cp.async.commit_group;" ::: "memory")
#define CP_WAIT(n)           asm volatile("cp.async.wait_group %0;" :: "n"(n) : "memory")

// arg = -d*g0*log2(e) (<= 0); 5-kernel sum via EX2 (MUFU) + repeated squaring
__device__ __forceinline__ float kern5e(float arg) {
    float e;
    asm("ex2.approx.ftz.f32 %0, %1;" : "=f"(e) : "f"(fminf(arg, 0.f)));
    float e2 = e * e, e4 = e2 * e2, e8 = e4 * e4;
    return e + e2 + e4 + e8 + e8 * e8;
}

// dynamic smem: [0,32K) A bufs, [32K,64K) B bufs, [64K,+512) sqj, then red[8]
#define SM_A     0
#define SM_B     32768
#define SM_SQJ   65536
#define SM_RED   66048
#define SMEM_TOTAL 66112

__global__ void __launch_bounds__(256, 2) mmd_fused(const float* __restrict__ S,
                                                    const float* __restrict__ T,
                                                    float* __restrict__ out) {
    extern __shared__ __align__(1024) uint8_t dsm[];
    const int tid = threadIdx.x;
    const int wid = tid >> 5, lane = tid & 31;
    __shared__ unsigned s_flag;

    // ================= Phase A: prologue, all 296 CTAs =================
    {
        float* cs = (float*)dsm;                // 1KB colsum partials
        float* ss = (float*)(dsm + 1024);       // 32B sumsq partials (per warp)
        cs[tid] = 0.f;
        if (tid < 8) ss[tid] = 0.f;
        __syncthreads();
        float cp[8] = {0.f, 0.f, 0.f, 0.f, 0.f, 0.f, 0.f, 0.f};
        float sqacc = 0.f;
        for (int row = blockIdx.x * 8 + wid; row < N2; row += GRID_MAIN * 8) {
            const float* F = (row < BATCH) ? (S + (size_t)row * D) : (T + (size_t)(row - BATCH) * D);
            float4 a = ((const float4*)F)[lane];
            float4 b = ((const float4*)F)[lane + 32];
            cp[0] += a.x; cp[1] += a.y; cp[2] += a.z; cp[3] += a.w;
            cp[4] += b.x; cp[5] += b.y; cp[6] += b.z; cp[7] += b.w;
            float s = a.x*a.x + a.y*a.y + a.z*a.z + a.w*a.w
                    + b.x*b.x + b.y*b.y + b.z*b.z + b.w*b.w;
            __half2* H = (__half2*)(g_half + (size_t)row * D);
            H[lane * 2 + 0]      = __floats2half2_rn(a.x, a.y);
            H[lane * 2 + 1]      = __floats2half2_rn(a.z, a.w);
            H[64 + lane * 2 + 0] = __floats2half2_rn(b.x, b.y);
            H[64 + lane * 2 + 1] = __floats2half2_rn(b.z, b.w);
            #pragma unroll
            for (int off = 16; off > 0; off >>= 1) s += __shfl_down_sync(0xffffffffu, s, off);
            if (lane == 0) { g_sq[row] = s; sqacc += s; }
        }
        #pragma unroll
        for (int q = 0; q < 4; ++q) atomicAdd(&cs[4 * lane + q], cp[q]);
        #pragma unroll
        for (int q = 0; q < 4; ++q) atomicAdd(&cs[128 + 4 * lane + q], cp[4 + q]);
        if (lane == 0) atomicAdd(&ss[wid], sqacc);
        __syncthreads();
        atomicAdd(&g_colsum[tid], (double)cs[tid]);
        if (tid == 0) {
            float s8 = ss[0] + ss[1] + ss[2] + ss[3] + ss[4] + ss[5] + ss[6] + ss[7];
            atomicAdd(&g_sum_sq, (double)s8);
        }

        __threadfence();
        if (tid == 0) s_flag = (atomicAdd(&g_cnt_pro, 1u) == GRID_MAIN - 1) ? 1u : 0u;
        __syncthreads();
        if (s_flag) {
            // last-arriving CTA: release mainloop FIRST, then compute g0 off-path
            if (tid == 0) atomicExch(&g_conv, 1u);
            double* rc = (double*)dsm;          // 2KB
            double v = g_colsum[tid];
            rc[tid] = v * v;
            g_colsum[tid] = 0.0;                // restore for next replay
            __syncthreads();
            for (int k = 128; k > 0; k >>= 1) {
                if (tid < k) rc[tid] += rc[tid + k];
                __syncthreads();
            }
            if (tid == 0) {
                double sum_dist = 2.0 * (double)N2 * g_sum_sq - 2.0 * rc[0];
                double bandwidth = ((double)N2 * (double)N2 - (double)N2) / sum_dist;
                g_g0 = (float)(bandwidth / 4.0);   // / 2^(NUM_KERNELS//2)
                g_sum_sq = 0.0;
                g_cnt_pro = 0;
                __threadfence();
                atomicExch(&g_ready, 1u);
            }
        }
    }

    // wait only for conversion (g0 computed concurrently with first tiles)
    if (tid == 0) {
        while (atomicAdd(&g_conv, 0u) == 0u) __nanosleep(32);
    }
    __syncthreads();

    // ================= Phase B: persistent HMMA mainloop =================
    float* sqj = (float*)(dsm + SM_SQJ);       // UNSCALED row norms of j-tile
    float* red = (float*)(dsm + SM_RED);
    const int wm = wid & 3, wn = wid >> 2;
    const int g = lane >> 2, j4 = lane & 3;
    const uint32_t sb = smem_u32(dsm);

    uint32_t aoff[2], boff[4];
    {
        int rA = wm * 32 + (lane & 15);
        int ca = (lane >> 4) * 16;
        #pragma unroll
        for (int mi = 0; mi < 2; ++mi) {
            uint32_t b0 = (uint32_t)((rA + mi * 16) * 128 + ca);
            aoff[mi] = b0 ^ ((b0 >> 3) & 0x70);
        }
        int rB = wn * 64 + (lane & 7) + ((lane >= 16) ? 8 : 0);
        int cb = (((lane >> 3) & 1) ? 16 : 0);
        #pragma unroll
        for (int nj = 0; nj < 4; ++nj) {
            uint32_t b0 = (uint32_t)((rB + nj * 16) * 128 + cb);
            boff[nj] = b0 ^ ((b0 >> 3) & 0x70);
        }
    }
    uint32_t stoff[4];
    #pragma unroll
    for (int r = 0; r < 4; ++r) {
        uint32_t b0 = (uint32_t)(((tid >> 3) + r * 32) * 128 + (tid & 7) * 16);
        stoff[r] = b0 ^ ((b0 >> 3) & 0x70);
    }
    const int ldrow = tid >> 3, ldf4 = tid & 7;

    float ngv = 0.f, m2ngv = 0.f;
    bool have_ng = false;
    double dacc = 0.0;

    int x = blockIdx.x;
    int bi = (int)((sqrtf(8.f * x + 1.f) - 1.f) * 0.5f);
    while ((bi + 1) * (bi + 2) / 2 <= x) bi++;
    while (bi * (bi + 1) / 2 > x) bi--;
    int bj = x - bi * (bi + 1) / 2;
    int i0 = bi * 128, j0 = bj * 128;

    // prefetch chunk 0 of first tile (one group)
    {
        const __half* pa = g_half + (size_t)(i0 + ldrow) * D + ldf4 * 8;
        const __half* pb = g_half + (size_t)(j0 + ldrow) * D + ldf4 * 8;
        #pragma unroll
        for (int r = 0; r < 4; ++r) {
            CP_ASYNC16(sb + SM_A + stoff[r], pa + (size_t)r * 32 * D);
            CP_ASYNC16(sb + SM_B + stoff[r], pb + (size_t)r * 32 * D);
        }
        CP_COMMIT();
    }

    for (; x < NBLK; x += GRID_MAIN) {
        int xn = x + GRID_MAIN;
        int i0n = 0, j0n = 0;
        const bool hasnext = xn < NBLK;
        if (hasnext) {
            int bin = (int)((sqrtf(8.f * xn + 1.f) - 1.f) * 0.5f);
            while ((bin + 1) * (bin + 2) / 2 <= xn) bin++;
            while (bin * (bin + 1) / 2 > xn) bin--;
            int bjn = xn - bin * (bin + 1) / 2;
            i0n = bin * 128; j0n = bjn * 128;
        }

        float acc[2][8][4];
        #pragma unroll
        for (int mi = 0; mi < 2; ++mi)
            #pragma unroll
            for (int ni = 0; ni < 8; ++ni)
                #pragma unroll
                for (int q = 0; q < 4; ++q) acc[mi][ni][q] = 0.f;

        #pragma unroll
        for (int c = 0; c < 4; ++c) {
            CP_WAIT(0);          // chunk c's data resident
            __syncthreads();     // also: all reads of the other buffer finished
            if (c == 0 && tid < 128) sqj[tid] = g_sq[j0 + tid];
            // prefetch one chunk ahead into the buffer just drained
            {
                int pi = i0, pj = j0, kc = (c + 1) * 64;
                bool doit = true;
                if (c == 3) { pi = i0n; pj = j0n; kc = 0; doit = hasnext; }
                if (doit) {
                    const uint32_t nbA = sb + SM_A + ((c + 1) & 1) * 16384;
                    const uint32_t nbB = sb + SM_B + ((c + 1) & 1) * 16384;
                    const __half* pa = g_half + (size_t)(pi + ldrow) * D + kc + ldf4 * 8;
                    const __half* pb = g_half + (size_t)(pj + ldrow) * D + kc + ldf4 * 8;
                    #pragma unroll
                    for (int r = 0; r < 4; ++r) {
                        CP_ASYNC16(nbA + stoff[r], pa + (size_t)r * 32 * D);
                        CP_ASYNC16(nbB + stoff[r], pb + (size_t)r * 32 * D);
                    }
                }
                CP_COMMIT();     // exactly one group per chunk (may be empty)
            }
            const uint32_t bufA = sb + SM_A + (c & 1) * 16384;
            const uint32_t bufB = sb + SM_B + (c & 1) * 16384;
            #pragma unroll
            for (int ks = 0; ks < 4; ++ks) {
                uint32_t a[2][4], b[4][4];
                #pragma unroll
                for (int mi = 0; mi < 2; ++mi)
                    asm volatile("ldmatrix.sync.aligned.m8n8.x4.shared.b16 {%0,%1,%2,%3}, [%4];"
                        : "=r"(a[mi][0]), "=r"(a[mi][1]), "=r"(a[mi][2]), "=r"(a[mi][3])
                        : "r"(bufA + (aoff[mi] ^ (ks * 32))));
                #pragma unroll
                for (int nj = 0; nj < 4; ++nj)
                    asm volatile("ldmatrix.sync.aligned.m8n8.x4.shared.b16 {%0,%1,%2,%3}, [%4];"
                        : "=r"(b[nj][0]), "=r"(b[nj][1]), "=r"(b[nj][2]), "=r"(b[nj][3])
                        : "r"(bufB + (boff[nj] ^ (ks * 32))));
                #pragma unroll
                for (int mi = 0; mi < 2; ++mi)
                    #pragma unroll
                    for (int ni = 0; ni < 8; ++ni) {
                        uint32_t b0 = b[ni >> 1][(ni & 1) * 2];
                        uint32_t b1 = b[ni >> 1][(ni & 1) * 2 + 1];
                        asm volatile(
                            "mma.sync.aligned.m16n8k16.row.col.f32.f16.f16.f32 "
                            "{%0,%1,%2,%3}, {%4,%5,%6,%7}, {%8,%9}, {%0,%1,%2,%3};"
                            : "+f"(acc[mi][ni][0]), "+f"(acc[mi][ni][1]),
                              "+f"(acc[mi][ni][2]), "+f"(acc[mi][ni][3])
                            : "r"(a[mi][0]), "r"(a[mi][1]), "r"(a[mi][2]), "r"(a[mi][3]),
                              "r"(b0), "r"(b1));
                    }
            }
        }

        // ---------------- epilogue (overlaps next tile's chunk-0 load) ----------------
        if (!have_ng) {   // uniform branch; first tile only
            if (tid == 0) {
                while (atomicAdd(&g_ready, 0u) == 0u) __nanosleep(32);
            }
            __syncthreads();
            ngv = -g_g0 * 1.44269504088896340736f;   // -g0*log2(e), < 0
            m2ngv = -2.f * ngv;
            have_ng = true;
        }
        float sing[2][2];
        #pragma unroll
        for (int mi = 0; mi < 2; ++mi) {
            sing[mi][0] = g_sq[i0 + wm * 32 + mi * 16 + g] * ngv;
            sing[mi][1] = g_sq[i0 + wm * 32 + mi * 16 + g + 8] * ngv;
        }
        float accsum = 0.f;
        #pragma unroll
        for (int mi = 0; mi < 2; ++mi)
            #pragma unroll
            for (int ni = 0; ni < 8; ++ni) {
                int cb = wn * 64 + ni * 8 + 2 * j4;
                float sj0 = sqj[cb], sj1 = sqj[cb + 1];
                float a0 = fmaf(sj0, ngv, sing[mi][0]);
                float a1 = fmaf(sj1, ngv, sing[mi][0]);
                float a2 = fmaf(sj0, ngv, sing[mi][1]);
                float a3 = fmaf(sj1, ngv, sing[mi][1]);
                accsum += kern5e(fmaf(acc[mi][ni][0], m2ngv, a0))
                        + kern5e(fmaf(acc[mi][ni][1], m2ngv, a1))
                        + kern5e(fmaf(acc[mi][ni][2], m2ngv, a2))
                        + kern5e(fmaf(acc[mi][ni][3], m2ngv, a3));
            }
        float w = (((i0 < BATCH) == (j0 < BATCH)) ? 1.f : -1.f) * ((bi == bj) ? 1.f : 2.f);
        accsum *= w;
        #pragma unroll
        for (int off = 16; off > 0; off >>= 1)
            accsum += __shfl_down_sync(0xffffffffu, accsum, off);
        if (lane == 0) red[wid] = accsum;
        __syncthreads();
        if (tid == 0) {
            float s = 0.f;
            #pragma unroll
            for (int i = 0; i < 8; ++i) s += red[i];
            dacc += (double)s;
        }
        // next tile's c==0 __syncthreads orders red/sqj reuse

        if (hasnext) {
            bi = (i0n >> 7); bj = (j0n >> 7);
            i0 = i0n; j0 = j0n;
        }
    }
    if (tid == 0) atomicAdd(&g_disc, dacc);

    // ---- last CTA writes the output and restores state for graph replay ----
    __threadfence();
    if (tid == 0) s_flag = (atomicAdd(&g_cnt_mma, 1u) == GRID_MAIN - 1) ? 1u : 0u;
    __syncthreads();
    if (s_flag && tid == 0) {
        double dsum = atomicAdd(&g_disc, 0.0);   // L2-coherent read
        out[0] = (float)(dsum / (5.0 * (double)BATCH * (double)BATCH));
        g_disc = 0.0;
        g_cnt_mma = 0;
        atomicExch(&g_conv, 0u);
        atomicExch(&g_ready, 0u);
    }
}

extern "C" void kernel_launch(void* const* d_in, const int* in_sizes, int n_in,
                              void* d_out, int out_size) {
    const float* S = (const float*)d_in[0];
    const float* T = (const float*)d_in[1];
    cudaFuncSetAttribute(mmd_fused, cudaFuncAttributeMaxDynamicSharedMemorySize, SMEM_TOTAL);
    mmd_fused<<<GRID_MAIN, 256, SMEM_TOTAL>>>(S, T, (float*)d_out);
}